// round 12
// baseline (speedup 1.0000x reference)
#include <cuda_runtime.h>

#define NN 50000
#define NE 800000
#define HCD 64
#define NTILES 49   // ceil(50000/1024)

// ---------------- scratch (static device globals; allocation-free) ----------
__device__ __align__(16) float g_xs[NN * HCD];      // xs of current layer
__device__ __align__(16) float g_h1[NN * HCD];      // relu(layer1 out)
__device__ __align__(16) float g_acc[NN * HCD];     // layer2 out (pre-pool)
__device__ __align__(16) float g_asrc[NN * 4];      // per-node a_src (4 heads)
__device__ __align__(16) float g_adst[NN * 4];      // per-node a_dst
__device__ __align__(16) float g_ce[8];             // [0..3] layer1, [4..7] layer2
// CSR build
__device__ int g_deg[NN];
__device__ int g_start[NN + 1];
__device__ int g_cursor[NN];
__device__ int g_bsum[NTILES];
__device__ __align__(16) int2 g_edge[NE];           // {src, ea bits} in CSR order

// ---------------- helpers ----------------------------------------------------
__device__ __forceinline__ float red16(float v) {
    v += __shfl_xor_sync(0xffffffffu, v, 8);
    v += __shfl_xor_sync(0xffffffffu, v, 4);
    v += __shfl_xor_sync(0xffffffffu, v, 2);
    v += __shfl_xor_sync(0xffffffffu, v, 1);
    return v;
}

// ---------------- hist (4 edges/thread) + fused ce constants -----------------
__global__ void k_hist(const int* __restrict__ ei,
                       const float* __restrict__ We1, const float* __restrict__ ae1,
                       const float* __restrict__ We2, const float* __restrict__ ae2) {
    if (blockIdx.x == 0 && threadIdx.x < 128) {
        int t = threadIdx.x;
        int layer = t >> 6;
        int c = t & 63;
        const float* We = layer ? We2 : We1;
        const float* ae = layer ? ae2 : ae1;
        float v = red16(We[c] * ae[c]);
        if ((c & 15) == 0) g_ce[layer * 4 + (c >> 4)] = v;
    }
    int t = blockIdx.x * blockDim.x + threadIdx.x;
    int e = t * 4;
    if (e >= NE) return;
    int4 d = *(const int4*)&ei[NE + e];
    atomicAdd(&g_deg[d.x], 1); atomicAdd(&g_deg[d.y], 1);
    atomicAdd(&g_deg[d.z], 1); atomicAdd(&g_deg[d.w], 1);
}

// ---------------- scan -------------------------------------------------------
__global__ void k_scanA() {           // per-tile reduction
    __shared__ int wsum[32];
    int b = blockIdx.x, tid = threadIdx.x, lane = tid & 31, w = tid >> 5;
    int i = b * 1024 + tid;
    int v = (i < NN) ? g_deg[i] : 0;
#pragma unroll
    for (int d = 16; d; d >>= 1) v += __shfl_xor_sync(0xffffffffu, v, d);
    if (lane == 0) wsum[w] = v;
    __syncthreads();
    if (w == 0) {
        int t = wsum[lane];
#pragma unroll
        for (int d = 16; d; d >>= 1) t += __shfl_xor_sync(0xffffffffu, t, d);
        if (lane == 0) g_bsum[b] = t;
    }
}

// per-tile scan + (redundant) scan of tile sums for the global offset.
// Cross-warp handoff uses BLOCK-level barriers.
__global__ void k_scanC() {
    __shared__ int wsum[32];
    __shared__ int sboff;
    __shared__ int ws2[2];
    int b = blockIdx.x, tid = threadIdx.x, lane = tid & 31, w = tid >> 5;

    int v2 = 0, x2 = 0;
    if (tid < 64) {
        v2 = (tid < NTILES) ? g_bsum[tid] : 0;
        x2 = v2;
#pragma unroll
        for (int d = 1; d < 32; d <<= 1) {
            int y = __shfl_up_sync(0xffffffffu, x2, d);
            if (lane >= d) x2 += y;
        }
        if (lane == 31) ws2[w] = x2;
    }
    __syncthreads();                       // publish ws2[0] to warp 1
    if (tid >= 32 && tid < 64) x2 += ws2[0];
    if (tid == b) sboff = x2 - v2;         // exclusive offset of this tile
    if (b == 0 && tid == NTILES - 1) g_start[NN] = x2;
    __syncthreads();                       // publish sboff

    int i = b * 1024 + tid;
    int v = (i < NN) ? g_deg[i] : 0;
    int x = v;
#pragma unroll
    for (int d = 1; d < 32; d <<= 1) {
        int y = __shfl_up_sync(0xffffffffu, x, d);
        if (lane >= d) x += y;
    }
    if (lane == 31) wsum[w] = x;
    __syncthreads();
    if (w == 0) {
        int t = wsum[lane];
#pragma unroll
        for (int d = 1; d < 32; d <<= 1) {
            int y = __shfl_up_sync(0xffffffffu, t, d);
            if (lane >= d) t += y;
        }
        wsum[lane] = t;
    }
    __syncthreads();
    int excl = sboff + (w ? wsum[w - 1] : 0) + x - v;
    if (i < NN) { g_start[i] = excl; g_cursor[i] = excl; }
}

// 4 edges per thread, vector loads; 782 blocks -> ~2x resident warps vs 8/thread.
__global__ void k_scatter(const int* __restrict__ ei, const float* __restrict__ ea) {
    int t = blockIdx.x * blockDim.x + threadIdx.x;
    int e = t * 4;
    if (e >= NE) return;
    int4   s4 = *(const int4*)&ei[e];
    int4   d4 = *(const int4*)&ei[NE + e];
    float4 a4 = *(const float4*)&ea[e];
    int p;
    p = atomicAdd(&g_cursor[d4.x], 1); g_edge[p] = make_int2(s4.x, __float_as_int(a4.x));
    p = atomicAdd(&g_cursor[d4.y], 1); g_edge[p] = make_int2(s4.y, __float_as_int(a4.y));
    p = atomicAdd(&g_cursor[d4.z], 1); g_edge[p] = make_int2(s4.z, __float_as_int(a4.z));
    p = atomicAdd(&g_cursor[d4.w], 1); g_edge[p] = make_int2(s4.w, __float_as_int(a4.w));
}

// ---------------- register-blocked linear ------------------------------------
template<int D>
__global__ void __launch_bounds__(256) k_linear(const float* __restrict__ Xext,
                                                const float* __restrict__ W,
                                                const float* __restrict__ as_,
                                                const float* __restrict__ ad_) {
    __shared__ float Wsh[D * 64];
    __shared__ float Xsh[128 * D];
    const float* X = Xext ? Xext : g_h1;
    int tid = threadIdx.x;
    int cg = tid & 7, ng = tid >> 3;
    int c0 = cg * 8;
    int h = cg >> 1;

    for (int i = tid * 4; i < D * 64; i += 1024)
        *(float4*)&Wsh[i] = *(const float4*)&W[i];

    int n0 = blockIdx.x * 128;
    int cnt = NN - n0; if (cnt > 128) cnt = 128;
    for (int i = tid * 4; i < cnt * D; i += 1024)
        *(float4*)&Xsh[i] = *(const float4*)&X[n0 * D + i];
    __syncthreads();

    float acc[4][8];
#pragma unroll
    for (int i = 0; i < 4; i++)
#pragma unroll
        for (int j = 0; j < 8; j++) acc[i][j] = 0.f;

#pragma unroll 2
    for (int k = 0; k < D; k++) {
        float4 wlo = *(const float4*)&Wsh[k * 64 + c0];
        float4 whi = *(const float4*)&Wsh[k * 64 + c0 + 4];
        float wr[8] = {wlo.x, wlo.y, wlo.z, wlo.w, whi.x, whi.y, whi.z, whi.w};
#pragma unroll
        for (int i = 0; i < 4; i++) {
            float xv = Xsh[(ng * 4 + i) * D + k];
#pragma unroll
            for (int j = 0; j < 8; j++)
                acc[i][j] = fmaf(xv, wr[j], acc[i][j]);
        }
    }

    float asv[8], adv[8];
#pragma unroll
    for (int j = 0; j < 8; j++) { asv[j] = as_[c0 + j]; adv[j] = ad_[c0 + j]; }

#pragma unroll
    for (int i = 0; i < 4; i++) {
        int node = n0 + ng * 4 + i;
        float ps = 0.f, pd = 0.f;
#pragma unroll
        for (int j = 0; j < 8; j++) {
            ps = fmaf(acc[i][j], asv[j], ps);
            pd = fmaf(acc[i][j], adv[j], pd);
        }
        ps += __shfl_xor_sync(0xffffffffu, ps, 1);
        pd += __shfl_xor_sync(0xffffffffu, pd, 1);
        if (node < NN) {
            float4 lo = make_float4(acc[i][0], acc[i][1], acc[i][2], acc[i][3]);
            float4 hi = make_float4(acc[i][4], acc[i][5], acc[i][6], acc[i][7]);
            *(float4*)&g_xs[node * HCD + c0] = lo;
            *(float4*)&g_xs[node * HCD + c0 + 4] = hi;
            if ((cg & 1) == 0) {
                g_asrc[node * 4 + h] = ps;
                g_adst[node * 4 + h] = pd;
            }
        }
    }
}

// ---------------- single-pass fused edge aggregation (one warp per dst) ------
// Unrolled x8: batch-load 8 edge records (4x int4), then 8 asrc + 8 xs gathers
// issued before any dependent math -> MLP ~16 outstanding loads per lane.
__global__ void k_edge_fused(int layer, const float* __restrict__ bias,
                             float* __restrict__ out, int relu) {
    int gw = (blockIdx.x * blockDim.x + threadIdx.x) >> 5;
    if (gw >= NN) return;
    int lane = threadIdx.x & 31;
    int c = lane * 2;               // two consecutive channels, same head
    int h = lane >> 3;
    int s0 = g_start[gw], s1 = g_start[gw + 1];

    float adh = g_adst[gw * 4 + h];
    float cfh = g_ce[layer * 4 + h];

    float acc0 = 0.f, acc1 = 0.f, dsum = 0.f;

    int j = s0;
    // align j to even so int4 loads of g_edge are 16B-aligned
    if (j < s1 && (j & 1)) {
        int2 ep = g_edge[j];
        float sh = g_asrc[ep.x * 4 + h];
        float2 xv = *(const float2*)&g_xs[ep.x * HCD + c];
        float t = sh + adh + cfh * __int_as_float(ep.y);
        t = t > 0.f ? t : 0.2f * t;
        float w = __expf(t);
        dsum += w;
        acc0 = fmaf(w, xv.x, acc0);
        acc1 = fmaf(w, xv.y, acc1);
        ++j;
    }
    for (; j + 7 < s1; j += 8) {
        int4 eA = *(const int4*)&g_edge[j];
        int4 eB = *(const int4*)&g_edge[j + 2];
        int4 eC = *(const int4*)&g_edge[j + 4];
        int4 eD = *(const int4*)&g_edge[j + 6];
        int n0i = eA.x, n1i = eA.z, n2i = eB.x, n3i = eB.z;
        int n4i = eC.x, n5i = eC.z, n6i = eD.x, n7i = eD.z;
        // issue all gathers up front
        float sh0 = g_asrc[n0i * 4 + h];
        float sh1 = g_asrc[n1i * 4 + h];
        float sh2 = g_asrc[n2i * 4 + h];
        float sh3 = g_asrc[n3i * 4 + h];
        float sh4 = g_asrc[n4i * 4 + h];
        float sh5 = g_asrc[n5i * 4 + h];
        float sh6 = g_asrc[n6i * 4 + h];
        float sh7 = g_asrc[n7i * 4 + h];
        float2 x0 = *(const float2*)&g_xs[n0i * HCD + c];
        float2 x1 = *(const float2*)&g_xs[n1i * HCD + c];
        float2 x2 = *(const float2*)&g_xs[n2i * HCD + c];
        float2 x3 = *(const float2*)&g_xs[n3i * HCD + c];
        float2 x4 = *(const float2*)&g_xs[n4i * HCD + c];
        float2 x5 = *(const float2*)&g_xs[n5i * HCD + c];
        float2 x6 = *(const float2*)&g_xs[n6i * HCD + c];
        float2 x7 = *(const float2*)&g_xs[n7i * HCD + c];
        float t0 = sh0 + adh + cfh * __int_as_float(eA.y);
        float t1 = sh1 + adh + cfh * __int_as_float(eA.w);
        float t2 = sh2 + adh + cfh * __int_as_float(eB.y);
        float t3 = sh3 + adh + cfh * __int_as_float(eB.w);
        float t4 = sh4 + adh + cfh * __int_as_float(eC.y);
        float t5 = sh5 + adh + cfh * __int_as_float(eC.w);
        float t6 = sh6 + adh + cfh * __int_as_float(eD.y);
        float t7 = sh7 + adh + cfh * __int_as_float(eD.w);
        t0 = t0 > 0.f ? t0 : 0.2f * t0;
        t1 = t1 > 0.f ? t1 : 0.2f * t1;
        t2 = t2 > 0.f ? t2 : 0.2f * t2;
        t3 = t3 > 0.f ? t3 : 0.2f * t3;
        t4 = t4 > 0.f ? t4 : 0.2f * t4;
        t5 = t5 > 0.f ? t5 : 0.2f * t5;
        t6 = t6 > 0.f ? t6 : 0.2f * t6;
        t7 = t7 > 0.f ? t7 : 0.2f * t7;
        float w0 = __expf(t0), w1 = __expf(t1), w2 = __expf(t2), w3 = __expf(t3);
        float w4 = __expf(t4), w5 = __expf(t5), w6 = __expf(t6), w7 = __expf(t7);
        dsum += ((w0 + w1) + (w2 + w3)) + ((w4 + w5) + (w6 + w7));
        acc0 = fmaf(w0, x0.x, acc0); acc1 = fmaf(w0, x0.y, acc1);
        acc0 = fmaf(w1, x1.x, acc0); acc1 = fmaf(w1, x1.y, acc1);
        acc0 = fmaf(w2, x2.x, acc0); acc1 = fmaf(w2, x2.y, acc1);
        acc0 = fmaf(w3, x3.x, acc0); acc1 = fmaf(w3, x3.y, acc1);
        acc0 = fmaf(w4, x4.x, acc0); acc1 = fmaf(w4, x4.y, acc1);
        acc0 = fmaf(w5, x5.x, acc0); acc1 = fmaf(w5, x5.y, acc1);
        acc0 = fmaf(w6, x6.x, acc0); acc1 = fmaf(w6, x6.y, acc1);
        acc0 = fmaf(w7, x7.x, acc0); acc1 = fmaf(w7, x7.y, acc1);
    }
    for (; j < s1; ++j) {
        int2 ep = g_edge[j];
        float sh = g_asrc[ep.x * 4 + h];
        float2 xv = *(const float2*)&g_xs[ep.x * HCD + c];
        float t = sh + adh + cfh * __int_as_float(ep.y);
        t = t > 0.f ? t : 0.2f * t;
        float w = __expf(t);
        dsum += w;
        acc0 = fmaf(w, xv.x, acc0);
        acc1 = fmaf(w, xv.y, acc1);
    }

    float rcp = (dsum > 0.f) ? (1.f / dsum) : 0.f;
    float2 bv = *(const float2*)&bias[c];
    float o0 = acc0 * rcp + bv.x;
    float o1 = acc1 * rcp + bv.y;
    if (relu) { o0 = fmaxf(o0, 0.f); o1 = fmaxf(o1, 0.f); }
    float2 ov; ov.x = o0; ov.y = o1;
    *(float2*)&out[gw * HCD + c] = ov;
}

// ---------------- pool (batch is sorted -> segment mean per graph) -----------
__device__ __forceinline__ int lowerb(const int* a, int n, int key) {
    int lo = 0, hi = n;
    while (lo < hi) { int m = (lo + hi) >> 1; if (a[m] < key) lo = m + 1; else hi = m; }
    return lo;
}

__global__ void k_pool(const int* __restrict__ batch, float* __restrict__ out) {
    int g = blockIdx.x;
    int lo = lowerb(batch, NN, g);
    int hi = lowerb(batch, NN, g + 1);
    int tid = threadIdx.x;             // 256
    int c = tid & 63, s = tid >> 6;    // 4 slices
    float acc = 0.f;
    for (int n = lo + s; n < hi; n += 4) acc += g_acc[n * HCD + c];
    __shared__ float sh[256];
    sh[tid] = acc;
    __syncthreads();
    if (s == 0) {
        float v = sh[c] + sh[c + 64] + sh[c + 128] + sh[c + 192];
        float cnt = (float)(hi - lo);
        out[g * HCD + c] = v / fmaxf(cnt, 1.f);
    }
}

// ---------------- launch -----------------------------------------------------
extern "C" void kernel_launch(void* const* d_in, const int* in_sizes, int n_in,
                              void* d_out, int out_size) {
    const float* x   = (const float*)d_in[0];
    const int*   ei  = (const int*)  d_in[1];
    const float* ea  = (const float*)d_in[2];
    const int*   bat = (const int*)  d_in[3];
    const float* W1  = (const float*)d_in[4];
    const float* We1 = (const float*)d_in[5];
    const float* as1 = (const float*)d_in[6];
    const float* ad1 = (const float*)d_in[7];
    const float* ae1 = (const float*)d_in[8];
    const float* b1  = (const float*)d_in[9];
    const float* W2  = (const float*)d_in[10];
    const float* We2 = (const float*)d_in[11];
    const float* as2 = (const float*)d_in[12];
    const float* ad2 = (const float*)d_in[13];
    const float* ae2 = (const float*)d_in[14];
    const float* b2  = (const float*)d_in[15];
    float* out = (float*)d_out;

    const int E4B = (NE / 4 + 255) / 256;          // 782 (4 edges/thread)
    const int FB  = (NN * 32 + 255) / 256;         // 6250 (one warp per node)
    const int LB  = (NN + 127) / 128;              // 391 linear tiles

    float *p_h1, *p_acc;
    int *p_deg;
    cudaGetSymbolAddress((void**)&p_h1,  g_h1);
    cudaGetSymbolAddress((void**)&p_acc, g_acc);
    cudaGetSymbolAddress((void**)&p_deg, g_deg);

    // Fork a side stream for the CSR build so it overlaps with k_linear<128>.
    cudaStream_t side = 0;
    cudaEvent_t evFork = 0, evJoin = 0;
    bool forked =
        (cudaStreamCreateWithFlags(&side, cudaStreamNonBlocking) == cudaSuccess) &&
        (cudaEventCreateWithFlags(&evFork, cudaEventDisableTiming) == cudaSuccess) &&
        (cudaEventCreateWithFlags(&evJoin, cudaEventDisableTiming) == cudaSuccess);

    cudaStream_t cs = forked ? side : 0;   // CSR stream

    if (forked) {
        cudaEventRecord(evFork, 0);            // fork point on capture stream
        cudaStreamWaitEvent(side, evFork, 0);
    }

    // ---- CSR build (side stream when forked) ----
    cudaMemsetAsync(p_deg, 0, NN * sizeof(int), cs);
    k_hist<<<E4B, 256, 0, cs>>>(ei, We1, ae1, We2, ae2);
    k_scanA<<<NTILES, 1024, 0, cs>>>();
    k_scanC<<<NTILES, 1024, 0, cs>>>();
    k_scatter<<<E4B, 256, 0, cs>>>(ei, ea);

    // ---- layer 1 linear (main stream, concurrent with CSR) ----
    k_linear<128><<<LB, 256>>>(x, W1, as1, ad1);

    if (forked) {
        cudaEventRecord(evJoin, side);         // join CSR chain back
        cudaStreamWaitEvent(0, evJoin, 0);
    }

    // ---- layer 1 aggregation ----
    k_edge_fused<<<FB, 256>>>(0, b1, p_h1, 1);

    // ---- layer 2 ----
    k_linear<64><<<LB, 256>>>(nullptr, W2, as2, ad2);
    k_edge_fused<<<FB, 256>>>(1, b2, p_acc, 0);

    // ---- pool ----
    k_pool<<<64, 256>>>(bat, out);
}

// round 13
// speedup vs baseline: 1.0939x; 1.0939x over previous
#include <cuda_runtime.h>

#define NN 50000
#define NE 800000
#define HCD 64
#define NTILES 49   // ceil(50000/1024)

// ---------------- scratch (static device globals; allocation-free) ----------
__device__ __align__(16) float g_xs[NN * HCD];      // xs of current layer
__device__ __align__(16) float g_h1[NN * HCD];      // relu(layer1 out)
__device__ __align__(16) float g_acc[NN * HCD];     // layer2 out (pre-pool)
__device__ __align__(16) float g_asrc[NN * 4];      // per-node a_src (4 heads)
__device__ __align__(16) float g_adst[NN * 4];      // per-node a_dst
__device__ __align__(16) float g_ce[8];             // [0..3] layer1, [4..7] layer2
// CSR build
__device__ int g_deg[NN];
__device__ int g_start[NN + 1];
__device__ int g_cursor[NN];
__device__ int g_bsum[NTILES];
__device__ __align__(16) int2 g_edge[NE];           // {src, ea bits} in CSR order

// ---------------- helpers ----------------------------------------------------
__device__ __forceinline__ float red16(float v) {
    v += __shfl_xor_sync(0xffffffffu, v, 8);
    v += __shfl_xor_sync(0xffffffffu, v, 4);
    v += __shfl_xor_sync(0xffffffffu, v, 2);
    v += __shfl_xor_sync(0xffffffffu, v, 1);
    return v;
}

// ---------------- hist (8 edges/thread) + fused ce constants -----------------
__global__ void k_hist(const int* __restrict__ ei,
                       const float* __restrict__ We1, const float* __restrict__ ae1,
                       const float* __restrict__ We2, const float* __restrict__ ae2) {
    if (blockIdx.x == 0 && threadIdx.x < 128) {
        int t = threadIdx.x;
        int layer = t >> 6;
        int c = t & 63;
        const float* We = layer ? We2 : We1;
        const float* ae = layer ? ae2 : ae1;
        float v = red16(We[c] * ae[c]);
        if ((c & 15) == 0) g_ce[layer * 4 + (c >> 4)] = v;
    }
    int t = blockIdx.x * blockDim.x + threadIdx.x;
    int e = t * 8;
    if (e >= NE) return;
    int4 d0 = *(const int4*)&ei[NE + e];
    int4 d1 = *(const int4*)&ei[NE + e + 4];
    atomicAdd(&g_deg[d0.x], 1); atomicAdd(&g_deg[d0.y], 1);
    atomicAdd(&g_deg[d0.z], 1); atomicAdd(&g_deg[d0.w], 1);
    atomicAdd(&g_deg[d1.x], 1); atomicAdd(&g_deg[d1.y], 1);
    atomicAdd(&g_deg[d1.z], 1); atomicAdd(&g_deg[d1.w], 1);
}

// ---------------- scan -------------------------------------------------------
__global__ void k_scanA() {           // per-tile reduction
    __shared__ int wsum[32];
    int b = blockIdx.x, tid = threadIdx.x, lane = tid & 31, w = tid >> 5;
    int i = b * 1024 + tid;
    int v = (i < NN) ? g_deg[i] : 0;
#pragma unroll
    for (int d = 16; d; d >>= 1) v += __shfl_xor_sync(0xffffffffu, v, d);
    if (lane == 0) wsum[w] = v;
    __syncthreads();
    if (w == 0) {
        int t = wsum[lane];
#pragma unroll
        for (int d = 16; d; d >>= 1) t += __shfl_xor_sync(0xffffffffu, t, d);
        if (lane == 0) g_bsum[b] = t;
    }
}

// per-tile scan + (redundant) scan of tile sums for the global offset.
// Cross-warp handoff uses BLOCK-level barriers.
__global__ void k_scanC() {
    __shared__ int wsum[32];
    __shared__ int sboff;
    __shared__ int ws2[2];
    int b = blockIdx.x, tid = threadIdx.x, lane = tid & 31, w = tid >> 5;

    int v2 = 0, x2 = 0;
    if (tid < 64) {
        v2 = (tid < NTILES) ? g_bsum[tid] : 0;
        x2 = v2;
#pragma unroll
        for (int d = 1; d < 32; d <<= 1) {
            int y = __shfl_up_sync(0xffffffffu, x2, d);
            if (lane >= d) x2 += y;
        }
        if (lane == 31) ws2[w] = x2;
    }
    __syncthreads();                       // publish ws2[0] to warp 1
    if (tid >= 32 && tid < 64) x2 += ws2[0];
    if (tid == b) sboff = x2 - v2;         // exclusive offset of this tile
    if (b == 0 && tid == NTILES - 1) g_start[NN] = x2;
    __syncthreads();                       // publish sboff

    int i = b * 1024 + tid;
    int v = (i < NN) ? g_deg[i] : 0;
    int x = v;
#pragma unroll
    for (int d = 1; d < 32; d <<= 1) {
        int y = __shfl_up_sync(0xffffffffu, x, d);
        if (lane >= d) x += y;
    }
    if (lane == 31) wsum[w] = x;
    __syncthreads();
    if (w == 0) {
        int t = wsum[lane];
#pragma unroll
        for (int d = 1; d < 32; d <<= 1) {
            int y = __shfl_up_sync(0xffffffffu, t, d);
            if (lane >= d) t += y;
        }
        wsum[lane] = t;
    }
    __syncthreads();
    int excl = sboff + (w ? wsum[w - 1] : 0) + x - v;
    if (i < NN) { g_start[i] = excl; g_cursor[i] = excl; }
}

// 8 edges per thread, vector loads for MLP.
__global__ void k_scatter(const int* __restrict__ ei, const float* __restrict__ ea) {
    int t = blockIdx.x * blockDim.x + threadIdx.x;
    int e = t * 8;
    if (e >= NE) return;
    int4   s0 = *(const int4*)&ei[e];
    int4   s1 = *(const int4*)&ei[e + 4];
    int4   d0 = *(const int4*)&ei[NE + e];
    int4   d1 = *(const int4*)&ei[NE + e + 4];
    float4 a0 = *(const float4*)&ea[e];
    float4 a1 = *(const float4*)&ea[e + 4];
    int p;
    p = atomicAdd(&g_cursor[d0.x], 1); g_edge[p] = make_int2(s0.x, __float_as_int(a0.x));
    p = atomicAdd(&g_cursor[d0.y], 1); g_edge[p] = make_int2(s0.y, __float_as_int(a0.y));
    p = atomicAdd(&g_cursor[d0.z], 1); g_edge[p] = make_int2(s0.z, __float_as_int(a0.z));
    p = atomicAdd(&g_cursor[d0.w], 1); g_edge[p] = make_int2(s0.w, __float_as_int(a0.w));
    p = atomicAdd(&g_cursor[d1.x], 1); g_edge[p] = make_int2(s1.x, __float_as_int(a1.x));
    p = atomicAdd(&g_cursor[d1.y], 1); g_edge[p] = make_int2(s1.y, __float_as_int(a1.y));
    p = atomicAdd(&g_cursor[d1.z], 1); g_edge[p] = make_int2(s1.z, __float_as_int(a1.z));
    p = atomicAdd(&g_cursor[d1.w], 1); g_edge[p] = make_int2(s1.w, __float_as_int(a1.w));
}

// ---------------- register-blocked linear ------------------------------------
template<int D>
__global__ void __launch_bounds__(256) k_linear(const float* __restrict__ Xext,
                                                const float* __restrict__ W,
                                                const float* __restrict__ as_,
                                                const float* __restrict__ ad_) {
    __shared__ float Wsh[D * 64];
    __shared__ float Xsh[128 * D];
    const float* X = Xext ? Xext : g_h1;
    int tid = threadIdx.x;
    int cg = tid & 7, ng = tid >> 3;
    int c0 = cg * 8;
    int h = cg >> 1;

    for (int i = tid * 4; i < D * 64; i += 1024)
        *(float4*)&Wsh[i] = *(const float4*)&W[i];

    int n0 = blockIdx.x * 128;
    int cnt = NN - n0; if (cnt > 128) cnt = 128;
    for (int i = tid * 4; i < cnt * D; i += 1024)
        *(float4*)&Xsh[i] = *(const float4*)&X[n0 * D + i];
    __syncthreads();

    float acc[4][8];
#pragma unroll
    for (int i = 0; i < 4; i++)
#pragma unroll
        for (int j = 0; j < 8; j++) acc[i][j] = 0.f;

#pragma unroll 2
    for (int k = 0; k < D; k++) {
        float4 wlo = *(const float4*)&Wsh[k * 64 + c0];
        float4 whi = *(const float4*)&Wsh[k * 64 + c0 + 4];
        float wr[8] = {wlo.x, wlo.y, wlo.z, wlo.w, whi.x, whi.y, whi.z, whi.w};
#pragma unroll
        for (int i = 0; i < 4; i++) {
            float xv = Xsh[(ng * 4 + i) * D + k];
#pragma unroll
            for (int j = 0; j < 8; j++)
                acc[i][j] = fmaf(xv, wr[j], acc[i][j]);
        }
    }

    float asv[8], adv[8];
#pragma unroll
    for (int j = 0; j < 8; j++) { asv[j] = as_[c0 + j]; adv[j] = ad_[c0 + j]; }

#pragma unroll
    for (int i = 0; i < 4; i++) {
        int node = n0 + ng * 4 + i;
        float ps = 0.f, pd = 0.f;
#pragma unroll
        for (int j = 0; j < 8; j++) {
            ps = fmaf(acc[i][j], asv[j], ps);
            pd = fmaf(acc[i][j], adv[j], pd);
        }
        ps += __shfl_xor_sync(0xffffffffu, ps, 1);
        pd += __shfl_xor_sync(0xffffffffu, pd, 1);
        if (node < NN) {
            float4 lo = make_float4(acc[i][0], acc[i][1], acc[i][2], acc[i][3]);
            float4 hi = make_float4(acc[i][4], acc[i][5], acc[i][6], acc[i][7]);
            *(float4*)&g_xs[node * HCD + c0] = lo;
            *(float4*)&g_xs[node * HCD + c0 + 4] = hi;
            if ((cg & 1) == 0) {
                g_asrc[node * 4 + h] = ps;
                g_adst[node * 4 + h] = pd;
            }
        }
    }
}

// ---------------- half-warp fused edge aggregation (one warp per dst) --------
// Lanes 0-15 process even edges, 16-31 odd edges; each lane owns 4 channels
// (float4). One int4 edge-record load serves both halves; one xs load
// instruction covers 2 edges (512B/warp). Each half accumulates its edges'
// softmax weights (lane-identical within a head group); a final shfl_xor(16)
// combines halves for both the denominator and the channel accumulators.
__global__ void k_edge_fused(int layer, const float* __restrict__ bias,
                             float* __restrict__ out, int relu) {
    int gw = (blockIdx.x * blockDim.x + threadIdx.x) >> 5;
    if (gw >= NN) return;
    int lane = threadIdx.x & 31;
    int half = lane >> 4;           // 0: even edges, 1: odd edges
    int l16 = lane & 15;
    int c0 = l16 * 4;               // 4 consecutive channels, single head
    int h = l16 >> 2;
    int s0 = g_start[gw], s1 = g_start[gw + 1];

    float adh = g_adst[gw * 4 + h];
    float cfh = g_ce[layer * 4 + h];

    float4 acc = make_float4(0.f, 0.f, 0.f, 0.f);
    float dsum = 0.f;

    int j = s0;
    // peel to even j so int4 loads of g_edge are 16B-aligned (half A only)
    if (j < s1 && (j & 1)) {
        if (half == 0) {
            int2 ep = g_edge[j];
            float sh = g_asrc[ep.x * 4 + h];
            float4 xv = *(const float4*)&g_xs[ep.x * HCD + c0];
            float t = sh + adh + cfh * __int_as_float(ep.y);
            t = t > 0.f ? t : 0.2f * t;
            float w = __expf(t);
            dsum += w;
            acc.x = fmaf(w, xv.x, acc.x); acc.y = fmaf(w, xv.y, acc.y);
            acc.z = fmaf(w, xv.z, acc.z); acc.w = fmaf(w, xv.w, acc.w);
        }
        ++j;
    }
    // 4 edges per iteration: 2 int4 record loads; each lane handles 2 edges.
    for (; j + 3 < s1; j += 4) {
        int4 eA = *(const int4*)&g_edge[j];       // edges j, j+1
        int4 eB = *(const int4*)&g_edge[j + 2];   // edges j+2, j+3
        int  srcA = half ? eA.z : eA.x;
        int  srcB = half ? eB.z : eB.x;
        float aA = __int_as_float(half ? eA.w : eA.y);
        float aB = __int_as_float(half ? eB.w : eB.y);
        float shA = g_asrc[srcA * 4 + h];
        float shB = g_asrc[srcB * 4 + h];
        float4 xA = *(const float4*)&g_xs[srcA * HCD + c0];
        float4 xB = *(const float4*)&g_xs[srcB * HCD + c0];
        float tA = shA + adh + cfh * aA;
        float tB = shB + adh + cfh * aB;
        tA = tA > 0.f ? tA : 0.2f * tA;
        tB = tB > 0.f ? tB : 0.2f * tB;
        float wA = __expf(tA), wB = __expf(tB);
        dsum += wA + wB;
        acc.x = fmaf(wA, xA.x, acc.x); acc.y = fmaf(wA, xA.y, acc.y);
        acc.z = fmaf(wA, xA.z, acc.z); acc.w = fmaf(wA, xA.w, acc.w);
        acc.x = fmaf(wB, xB.x, acc.x); acc.y = fmaf(wB, xB.y, acc.y);
        acc.z = fmaf(wB, xB.z, acc.z); acc.w = fmaf(wB, xB.w, acc.w);
    }
    // 2-edge step
    if (j + 1 < s1) {
        int4 eA = *(const int4*)&g_edge[j];
        int  src = half ? eA.z : eA.x;
        float a = __int_as_float(half ? eA.w : eA.y);
        float sh = g_asrc[src * 4 + h];
        float4 xv = *(const float4*)&g_xs[src * HCD + c0];
        float t = sh + adh + cfh * a;
        t = t > 0.f ? t : 0.2f * t;
        float w = __expf(t);
        dsum += w;
        acc.x = fmaf(w, xv.x, acc.x); acc.y = fmaf(w, xv.y, acc.y);
        acc.z = fmaf(w, xv.z, acc.z); acc.w = fmaf(w, xv.w, acc.w);
        j += 2;
    }
    // single tail edge (half A only)
    if (j < s1 && half == 0) {
        int2 ep = g_edge[j];
        float sh = g_asrc[ep.x * 4 + h];
        float4 xv = *(const float4*)&g_xs[ep.x * HCD + c0];
        float t = sh + adh + cfh * __int_as_float(ep.y);
        t = t > 0.f ? t : 0.2f * t;
        float w = __expf(t);
        dsum += w;
        acc.x = fmaf(w, xv.x, acc.x); acc.y = fmaf(w, xv.y, acc.y);
        acc.z = fmaf(w, xv.z, acc.z); acc.w = fmaf(w, xv.w, acc.w);
    }

    // combine halves (full-warp collective)
    dsum  += __shfl_xor_sync(0xffffffffu, dsum, 16);
    acc.x += __shfl_xor_sync(0xffffffffu, acc.x, 16);
    acc.y += __shfl_xor_sync(0xffffffffu, acc.y, 16);
    acc.z += __shfl_xor_sync(0xffffffffu, acc.z, 16);
    acc.w += __shfl_xor_sync(0xffffffffu, acc.w, 16);

    if (half == 0) {
        float rcp = (dsum > 0.f) ? (1.f / dsum) : 0.f;
        float4 bv = *(const float4*)&bias[c0];
        float4 ov;
        ov.x = acc.x * rcp + bv.x;
        ov.y = acc.y * rcp + bv.y;
        ov.z = acc.z * rcp + bv.z;
        ov.w = acc.w * rcp + bv.w;
        if (relu) {
            ov.x = fmaxf(ov.x, 0.f); ov.y = fmaxf(ov.y, 0.f);
            ov.z = fmaxf(ov.z, 0.f); ov.w = fmaxf(ov.w, 0.f);
        }
        *(float4*)&out[gw * HCD + c0] = ov;
    }
}

// ---------------- pool (batch is sorted -> segment mean per graph) -----------
__device__ __forceinline__ int lowerb(const int* a, int n, int key) {
    int lo = 0, hi = n;
    while (lo < hi) { int m = (lo + hi) >> 1; if (a[m] < key) lo = m + 1; else hi = m; }
    return lo;
}

__global__ void k_pool(const int* __restrict__ batch, float* __restrict__ out) {
    int g = blockIdx.x;
    int lo = lowerb(batch, NN, g);
    int hi = lowerb(batch, NN, g + 1);
    int tid = threadIdx.x;             // 256
    int c = tid & 63, s = tid >> 6;    // 4 slices
    float acc = 0.f;
    for (int n = lo + s; n < hi; n += 4) acc += g_acc[n * HCD + c];
    __shared__ float sh[256];
    sh[tid] = acc;
    __syncthreads();
    if (s == 0) {
        float v = sh[c] + sh[c + 64] + sh[c + 128] + sh[c + 192];
        float cnt = (float)(hi - lo);
        out[g * HCD + c] = v / fmaxf(cnt, 1.f);
    }
}

// ---------------- launch -----------------------------------------------------
extern "C" void kernel_launch(void* const* d_in, const int* in_sizes, int n_in,
                              void* d_out, int out_size) {
    const float* x   = (const float*)d_in[0];
    const int*   ei  = (const int*)  d_in[1];
    const float* ea  = (const float*)d_in[2];
    const int*   bat = (const int*)  d_in[3];
    const float* W1  = (const float*)d_in[4];
    const float* We1 = (const float*)d_in[5];
    const float* as1 = (const float*)d_in[6];
    const float* ad1 = (const float*)d_in[7];
    const float* ae1 = (const float*)d_in[8];
    const float* b1  = (const float*)d_in[9];
    const float* W2  = (const float*)d_in[10];
    const float* We2 = (const float*)d_in[11];
    const float* as2 = (const float*)d_in[12];
    const float* ad2 = (const float*)d_in[13];
    const float* ae2 = (const float*)d_in[14];
    const float* b2  = (const float*)d_in[15];
    float* out = (float*)d_out;

    const int E8B = (NE / 8 + 255) / 256;          // 391 (8 edges/thread)
    const int FB  = (NN * 32 + 255) / 256;         // 6250 (one warp per node)
    const int LB  = (NN + 127) / 128;              // 391 linear tiles

    float *p_h1, *p_acc;
    int *p_deg;
    cudaGetSymbolAddress((void**)&p_h1,  g_h1);
    cudaGetSymbolAddress((void**)&p_acc, g_acc);
    cudaGetSymbolAddress((void**)&p_deg, g_deg);

    // Fork a side stream for the CSR build so it overlaps with k_linear<128>.
    cudaStream_t side = 0;
    cudaEvent_t evFork = 0, evJoin = 0;
    bool forked =
        (cudaStreamCreateWithFlags(&side, cudaStreamNonBlocking) == cudaSuccess) &&
        (cudaEventCreateWithFlags(&evFork, cudaEventDisableTiming) == cudaSuccess) &&
        (cudaEventCreateWithFlags(&evJoin, cudaEventDisableTiming) == cudaSuccess);

    cudaStream_t cs = forked ? side : 0;   // CSR stream

    if (forked) {
        cudaEventRecord(evFork, 0);            // fork point on capture stream
        cudaStreamWaitEvent(side, evFork, 0);
    }

    // ---- CSR build (side stream when forked) ----
    cudaMemsetAsync(p_deg, 0, NN * sizeof(int), cs);
    k_hist<<<E8B, 256, 0, cs>>>(ei, We1, ae1, We2, ae2);
    k_scanA<<<NTILES, 1024, 0, cs>>>();
    k_scanC<<<NTILES, 1024, 0, cs>>>();
    k_scatter<<<E8B, 256, 0, cs>>>(ei, ea);

    // ---- layer 1 linear (main stream, concurrent with CSR) ----
    k_linear<128><<<LB, 256>>>(x, W1, as1, ad1);

    if (forked) {
        cudaEventRecord(evJoin, side);         // join CSR chain back
        cudaStreamWaitEvent(0, evJoin, 0);
    }

    // ---- layer 1 aggregation ----
    k_edge_fused<<<FB, 256>>>(0, b1, p_h1, 1);

    // ---- layer 2 ----
    k_linear<64><<<LB, 256>>>(nullptr, W2, as2, ad2);
    k_edge_fused<<<FB, 256>>>(1, b2, p_acc, 0);

    // ---- pool ----
    k_pool<<<64, 256>>>(bat, out);
}